// round 4
// baseline (speedup 1.0000x reference)
#include <cuda_runtime.h>
#include <cuda_bf16.h>
#include <cstdint>
#include <math.h>

#define NROW 8192
#define MROW 8192
#define DDIM 256
#define NT 32          // column tiles per CTA
#define TILE 128

// Scratch: e4m3 fp8, stored PRE-SWIZZLED in 32KB blocks of 128 rows:
// block = 2 K-chunks of [128 rows x 128 fp8] (128B rows), SW128-swizzled.
__device__ uint4 g_pk[NROW * 16];   // 256 B/row = 16 uint4
__device__ uint4 g_nv[MROW * 16];
__device__ float g_pos[NROW];
__device__ float g_rowsum[NROW];

// ---------------------------------------------------------------------------
__device__ __forceinline__ uint32_t smem_u32(const void* p) {
    uint32_t a;
    asm("{ .reg .u64 t; cvta.to.shared.u64 t, %1; cvt.u32.u64 %0, t; }" : "=r"(a) : "l"(p));
    return a;
}
__device__ __forceinline__ uint32_t elect_one() {
    uint32_t p;
    asm volatile("{\n\t.reg .pred p;\n\telect.sync _|p, 0xFFFFFFFF;\n\tselp.b32 %0,1,0,p;\n\t}" : "=r"(p));
    return p;
}
__device__ __forceinline__ float ex2(float x) {
    float r;
    asm("ex2.approx.ftz.f32 %0, %1;" : "=f"(r) : "f"(x));
    return r;
}
// pack 2 floats -> e4m3x2 (first source -> high byte)
__device__ __forceinline__ uint32_t f2_e4m3(float hi, float lo) {
    uint32_t r;
    asm("{ .reg .b16 t; cvt.rn.satfinite.e4m3x2.f32 t, %1, %2; cvt.u32.u16 %0, t; }"
        : "=r"(r) : "f"(hi), "f"(lo));
    return r;
}
#define MBAR_INIT(a, c) asm volatile("mbarrier.init.shared.b64 [%0], %1;" :: "r"(a), "r"(c) : "memory")
#define MBAR_EXPECT(a, n) asm volatile("mbarrier.arrive.expect_tx.shared.b64 _, [%0], %1;" :: "r"(a), "r"(n) : "memory")
#define MBAR_WAIT(a, ph) do {                                                           \
    asm volatile("{\n\t.reg .pred P1;\n\t"                                              \
                 "WL%=:\n\t"                                                            \
                 "mbarrier.try_wait.parity.acquire.cta.shared::cta.b64 P1, [%0], %1, 0x989680;\n\t" \
                 "@P1 bra.uni WD%=;\n\t"                                                \
                 "bra.uni WL%=;\n\t"                                                    \
                 "WD%=:\n\t}" :: "r"(a), "r"(ph) : "memory");                           \
} while (0)
#define BULK_LD(dst, src, bytes, mbar) asm volatile( \
    "cp.async.bulk.shared::cluster.global.mbarrier::complete_tx::bytes [%0], [%1], %2, [%3];" \
    :: "r"(dst), "l"(src), "r"(bytes), "r"(mbar) : "memory")

__device__ __forceinline__ void mma_fp8(float* d, const uint32_t* a, uint32_t b0, uint32_t b1) {
    asm volatile(
        "mma.sync.aligned.m16n8k32.row.col.f32.e4m3.e4m3.f32 "
        "{%0,%1,%2,%3},{%4,%5,%6,%7},{%8,%9},{%0,%1,%2,%3};\n"
        : "+f"(d[0]), "+f"(d[1]), "+f"(d[2]), "+f"(d[3])
        : "r"(a[0]), "r"(a[1]), "r"(a[2]), "r"(a[3]), "r"(b0), "r"(b1));
}

// ---------------------------------------------------------------------------
// Kernel 1: normalize -> e4m3, write PRE-SWIZZLED tile-block layout.
// 1 warp per row; lane L owns elems [8L, 8L+8) (8 floats -> 8 bytes).
// chunk = L>>4 (128 elems each), in-chunk byte off = rowIn*128 + (L&15)*8.
// ---------------------------------------------------------------------------
__device__ __forceinline__ void store_sw8(uint4* g, int row, int lane, uint2 v) {
    int blk = row >> 7, rowIn = row & 127;
    uint32_t off = (uint32_t)(rowIn * 128 + (lane & 15) * 8);
    off = off ^ ((off >> 3) & 0x70);
    *reinterpret_cast<uint2*>(
        reinterpret_cast<char*>(g) + (size_t)blk * 32768 + (lane >> 4) * 16384 + off) = v;
}

__global__ void __launch_bounds__(256) prep_kernel(const float4* __restrict__ pk,
                                                   const float4* __restrict__ pv,
                                                   const float4* __restrict__ nv) {
    const int row = blockIdx.x * 8 + (threadIdx.x >> 5);
    const int lane = threadIdx.x & 31;

    if (row < NROW) {
        float4 k0 = pk[row * 64 + 2 * lane], k1 = pk[row * 64 + 2 * lane + 1];
        float4 v0 = pv[row * 64 + 2 * lane], v1 = pv[row * 64 + 2 * lane + 1];
        float ssk = k0.x*k0.x + k0.y*k0.y + k0.z*k0.z + k0.w*k0.w
                  + k1.x*k1.x + k1.y*k1.y + k1.z*k1.z + k1.w*k1.w;
        float ssv = v0.x*v0.x + v0.y*v0.y + v0.z*v0.z + v0.w*v0.w
                  + v1.x*v1.x + v1.y*v1.y + v1.z*v1.z + v1.w*v1.w;
        float dkv = k0.x*v0.x + k0.y*v0.y + k0.z*v0.z + k0.w*v0.w
                  + k1.x*v1.x + k1.y*v1.y + k1.z*v1.z + k1.w*v1.w;
        #pragma unroll
        for (int o = 16; o > 0; o >>= 1) {
            ssk += __shfl_xor_sync(0xffffffffu, ssk, o);
            ssv += __shfl_xor_sync(0xffffffffu, ssv, o);
            dkv += __shfl_xor_sync(0xffffffffu, dkv, o);
        }
        float sk = 1.0f / fmaxf(sqrtf(ssk), 1e-8f);
        float sv = 1.0f / fmaxf(sqrtf(ssv), 1e-8f);
        uint32_t p0 = f2_e4m3(k0.y*sk, k0.x*sk) | (f2_e4m3(k0.w*sk, k0.z*sk) << 16);
        uint32_t p1 = f2_e4m3(k1.y*sk, k1.x*sk) | (f2_e4m3(k1.w*sk, k1.z*sk) << 16);
        store_sw8(g_pk, row, lane, make_uint2(p0, p1));
        if (lane == 0) {
            g_pos[row] = dkv * sk * sv;
            g_rowsum[row] = 0.0f;
        }
    } else {
        const int r = row - NROW;
        float4 x0 = nv[r * 64 + 2 * lane], x1 = nv[r * 64 + 2 * lane + 1];
        float ss = x0.x*x0.x + x0.y*x0.y + x0.z*x0.z + x0.w*x0.w
                 + x1.x*x1.x + x1.y*x1.y + x1.z*x1.z + x1.w*x1.w;
        #pragma unroll
        for (int o = 16; o > 0; o >>= 1)
            ss += __shfl_xor_sync(0xffffffffu, ss, o);
        float s = 1.0f / fmaxf(sqrtf(ss), 1e-8f);
        uint32_t p0 = f2_e4m3(x0.y*s, x0.x*s) | (f2_e4m3(x0.w*s, x0.z*s) << 16);
        uint32_t p1 = f2_e4m3(x1.y*s, x1.x*s) | (f2_e4m3(x1.w*s, x1.z*s) << 16);
        store_sw8(g_nv, r, lane, make_uint2(p0, p1));
    }
}

// ---------------------------------------------------------------------------
// Kernel 2: pipelined FP8 mma.sync GEMM + fused exp(sim/2) row-sums.
// 128 CTAs (64 rowblocks x 2 col halves), 256 thr. A (32KB) resident,
// A-frags in registers; B double-buffered via cp.async.bulk.
// Warp w owns rows [16w,16w+16) x all 128 cols. 8 k-steps of m16n8k32.
// ---------------------------------------------------------------------------
__global__ void __launch_bounds__(256, 1) gemm_lse_kernel() {
    extern __shared__ __align__(1024) char dsmem[];
    __shared__ __align__(8) uint64_t s_mbar[3];   // fullB0, fullB1, fullA

    const int tid = threadIdx.x;
    const int warp = tid >> 5;
    const int lane = tid & 31;
    const int rowblk = blockIdx.x >> 1;
    const int colhalf = blockIdx.x & 1;
    const int rowbase = rowblk * TILE;
    const int ctbase = colhalf * NT;

    uint32_t sb = smem_u32(dsmem);
    const uint32_t aBase = (sb + 1023u) & ~1023u;
    const uint32_t bBase[2] = {aBase + 32768u, aBase + 65536u};
    const uint32_t mbB[2] = {smem_u32(&s_mbar[0]), smem_u32(&s_mbar[1])};
    const uint32_t mbA = smem_u32(&s_mbar[2]);

    if (tid == 0) {
        MBAR_INIT(mbB[0], 1);
        MBAR_INIT(mbB[1], 1);
        MBAR_INIT(mbA, 1);
    }
    __syncthreads();

    if (warp == 0 && elect_one()) {
        MBAR_EXPECT(mbA, 32768u);
        BULK_LD(aBase, (const char*)g_pk + (size_t)rowblk * 32768, 32768u, mbA);
        MBAR_EXPECT(mbB[0], 32768u);
        BULK_LD(bBase[0], (const char*)g_nv + (size_t)ctbase * 32768, 32768u, mbB[0]);
    }

    // ---- A fragments into registers (held for whole kernel) ----
    // kstep = 32B; chunk = ks>>2 (16KB each); in-chunk col byte = (ks&3)*32.
    uint32_t afr[8][4];
    {
        MBAR_WAIT(mbA, 0);
        const int arow = warp * 16 + (lane & 7) + ((lane >> 3) & 1) * 8;
        const uint32_t rx = (uint32_t)((arow & 7) << 4);
        const uint32_t rb = (uint32_t)(arow * 128);
        const uint32_t lnc = (uint32_t)((lane >> 4) << 4);
        #pragma unroll
        for (int ks = 0; ks < 8; ks++) {
            uint32_t addr = aBase + ((ks >> 2) << 14) + rb
                          + ((((uint32_t)(ks & 3) << 5) | lnc) ^ rx);
            asm volatile("ldmatrix.sync.aligned.m8n8.x4.shared.b16 {%0,%1,%2,%3},[%4];"
                         : "=r"(afr[ks][0]), "=r"(afr[ks][1]), "=r"(afr[ks][2]), "=r"(afr[ks][3])
                         : "r"(addr));
        }
    }

    // B ldmatrix per-lane address components (pair j covers n = 16j .. 16j+15)
    uint32_t brb[8], brx[8];
    {
        const int nr = (lane & 7) + ((lane >> 3) & 1) * 8;
        #pragma unroll
        for (int j = 0; j < 8; j++) {
            int r = j * 16 + nr;
            brb[j] = (uint32_t)(r * 128);
            brx[j] = (uint32_t)((r & 7) << 4) ^ (uint32_t)((lane >> 4) << 4);
        }
    }

    float acc[16][4];
    #pragma unroll
    for (int g = 0; g < 16; g++)
        #pragma unroll
        for (int c = 0; c < 4; c++) acc[g][c] = 0.0f;

    float rowacc0 = 0.0f, rowacc1 = 0.0f;
    const float C = 0.72134752044448170f;  // log2(e)/2

    for (int t = 0; t < NT; t++) {
        __syncthreads();   // everyone done reading buf[(t+1)&1] (used at t-1)
        if (t + 1 < NT && warp == 0 && elect_one()) {
            MBAR_EXPECT(mbB[(t + 1) & 1], 32768u);
            BULK_LD(bBase[(t + 1) & 1],
                    (const char*)g_nv + (size_t)(ctbase + t + 1) * 32768, 32768u,
                    mbB[(t + 1) & 1]);
        }
        MBAR_WAIT(mbB[t & 1], (t >> 1) & 1);

        const uint32_t bb = bBase[t & 1];
        #pragma unroll
        for (int ks = 0; ks < 8; ks++) {
            const uint32_t kch = bb + ((ks >> 2) << 14);
            const uint32_t kcol = (uint32_t)((ks & 3) << 5);
            uint32_t b[8][4];
            #pragma unroll
            for (int j = 0; j < 8; j++) {
                uint32_t addr = kch + brb[j] + (kcol ^ brx[j]);
                asm volatile("ldmatrix.sync.aligned.m8n8.x4.shared.b16 {%0,%1,%2,%3},[%4];"
                             : "=r"(b[j][0]), "=r"(b[j][1]), "=r"(b[j][2]), "=r"(b[j][3])
                             : "r"(addr));
            }
            #pragma unroll
            for (int j = 0; j < 8; j++) {
                mma_fp8(acc[2 * j],     afr[ks], b[j][0], b[j][2]);
                mma_fp8(acc[2 * j + 1], afr[ks], b[j][1], b[j][3]);
            }
        }

        // fused epilogue: rowsum += exp2(sim * log2e/2); reset acc
        float s0 = 0.0f, s1 = 0.0f;
        #pragma unroll
        for (int g = 0; g < 16; g++) {
            s0 += ex2(acc[g][0] * C) + ex2(acc[g][1] * C);
            s1 += ex2(acc[g][2] * C) + ex2(acc[g][3] * C);
            acc[g][0] = 0.0f; acc[g][1] = 0.0f; acc[g][2] = 0.0f; acc[g][3] = 0.0f;
        }
        rowacc0 += s0;
        rowacc1 += s1;
    }

    // reduce across the 4 lanes sharing a row, then one global atomic per row
    rowacc0 += __shfl_xor_sync(0xffffffffu, rowacc0, 1);
    rowacc0 += __shfl_xor_sync(0xffffffffu, rowacc0, 2);
    rowacc1 += __shfl_xor_sync(0xffffffffu, rowacc1, 1);
    rowacc1 += __shfl_xor_sync(0xffffffffu, rowacc1, 2);
    if ((lane & 3) == 0) {
        int r = rowbase + warp * 16 + (lane >> 2);
        atomicAdd(&g_rowsum[r], rowacc0);
        atomicAdd(&g_rowsum[r + 8], rowacc1);
    }
}

// ---------------------------------------------------------------------------
// Kernel 3: loss = mean(log(rowsum)) - 0.5 * mean(pos_sim)
// ---------------------------------------------------------------------------
__global__ void __launch_bounds__(1024) reduce_kernel(float* __restrict__ out) {
    __shared__ float sl[32], sp[32];
    const int tid = threadIdx.x;
    float ls = 0.0f, ps = 0.0f;
    for (int i = tid; i < NROW; i += 1024) {
        ls += logf(g_rowsum[i]);
        ps += g_pos[i];
    }
    #pragma unroll
    for (int o = 16; o > 0; o >>= 1) {
        ls += __shfl_xor_sync(0xffffffffu, ls, o);
        ps += __shfl_xor_sync(0xffffffffu, ps, o);
    }
    const int lane = tid & 31, warp = tid >> 5;
    if (lane == 0) { sl[warp] = ls; sp[warp] = ps; }
    __syncthreads();
    if (warp == 0) {
        ls = sl[lane];
        ps = sp[lane];
        #pragma unroll
        for (int o = 16; o > 0; o >>= 1) {
            ls += __shfl_xor_sync(0xffffffffu, ls, o);
            ps += __shfl_xor_sync(0xffffffffu, ps, o);
        }
        if (lane == 0)
            out[0] = ls * (1.0f / NROW) - 0.5f * ps * (1.0f / NROW);
    }
}

// ---------------------------------------------------------------------------
extern "C" void kernel_launch(void* const* d_in, const int* in_sizes, int n_in,
                              void* d_out, int out_size) {
    const float4* pk = reinterpret_cast<const float4*>(d_in[0]);
    const float4* pv = reinterpret_cast<const float4*>(d_in[1]);
    const float4* nv = reinterpret_cast<const float4*>(d_in[2]);
    float* out = reinterpret_cast<float*>(d_out);

    const int smem_bytes = 1024 + 3 * 32768;  // pad + A + 2x B
    cudaFuncSetAttribute(gemm_lse_kernel,
                         cudaFuncAttributeMaxDynamicSharedMemorySize, smem_bytes);

    prep_kernel<<<(NROW + MROW) / 8, 256>>>(pk, pv, nv);
    gemm_lse_kernel<<<128, 256, smem_bytes>>>();
    reduce_kernel<<<1, 1024>>>(out);
}